// round 13
// baseline (speedup 1.0000x reference)
#include <cuda_runtime.h>

#define NUM_CLS 32000
#define BATCH   4096
#define C4      (NUM_CLS / 4)   // 8000 float4 per row
#define HALF4   (C4 / 2)        // 4000 — half-row rotation for the t stream
#define THREADS 512
#define NWARP   (THREADS / 32)  // 16
#define NBLOCKS 592             // 148 SMs x 4 resident CTAs — persistent grid

// Per-row partial results (deterministic; no float atomics).
__device__ float g_row[BATCH];
// Completion counter; last block resets it so graph replays start clean.
__device__ unsigned int g_done;

__global__ __launch_bounds__(THREADS, 4)
void rce_fused_kernel(const float* __restrict__ inp,
                      const float* __restrict__ tgt,
                      float* __restrict__ out)
{
    const int wid = threadIdx.x >> 5;
    const int lid = threadIdx.x & 31;

    // Double-buffered per-warp partials (parity = row counter & 1).
    // The single per-row __syncthreads orders: writes of buffer p (iter k,
    // pre-barrier) -> reads of buffer p (iter k, post-barrier) -> next write
    // of buffer p (iter k+2, after barrier k+1). No second barrier needed.
    __shared__ float    sh_s[2][NWARP];
    __shared__ float    sh_e[2][NWARP];
    __shared__ unsigned sh_b[2][NWARP];
    __shared__ unsigned sh_i[2][NWARP];
    __shared__ bool     sh_last;

    int k = 0;
    for (int row = blockIdx.x; row < BATCH; row += NBLOCKS, ++k) {
        const int p = k & 1;
        const float4* ip = reinterpret_cast<const float4*>(inp + (size_t)row * NUM_CLS);
        const float4* tp = reinterpret_cast<const float4*>(tgt + (size_t)row * NUM_CLS);

        float s_sum = 0.f;                 // sum of x
        float e_sum = 0.f;                 // sum of exp(-x)
        unsigned cur_bits = 0xffffffffu;   // running min of target bits (t >= 0
        unsigned cur_idx  = 0xffffffffu;   //  -> float bits order-preserving)

        #pragma unroll 4
        for (int i = threadIdx.x; i < C4; i += THREADS) {
            // De-phase the target stream by half a row (16 KB): ip[i] and
            // tp[i] live at equal intra-array offsets of two 512MB-apart
            // allocations, so they hash to the SAME LTS slice/DRAM channel
            // (hash uses bits {8,10-27} only). The +16KB rotation flips
            // bit 14 -> the paired loads hit different slices. Union over
            // threads still covers every quad exactly once; consecutive
            // lanes stay consecutive (coalescing intact).
            int j = i + HALF4;
            if (j >= C4) j -= C4;

            const float4 x = ip[i];
            const float4 t = tp[j];

            s_sum += (x.x + x.y) + (x.z + x.w);
            e_sum += (__expf(-x.x) + __expf(-x.y)) + (__expf(-x.z) + __expf(-x.w));

            const unsigned b0 = __float_as_uint(t.x);
            const unsigned b1 = __float_as_uint(t.y);
            const unsigned b2 = __float_as_uint(t.z);
            const unsigned b3 = __float_as_uint(t.w);
            // Quad-local argmin, first index wins ties.
            const unsigned m01 = min(b0, b1);
            const unsigned i01 = (b1 < b0) ? 1u : 0u;
            const unsigned m23 = min(b2, b3);
            const unsigned i23 = (b3 < b2) ? 3u : 2u;
            const unsigned m   = min(m01, m23);
            const unsigned iq  = (m23 < m01) ? i23 : i01;
            // Visit order is no longer ascending per thread (rotation), so
            // break ties lexicographically on (value bits, index) — same
            // rule as the cross-thread combine; preserves first-occurrence.
            const unsigned idx = (unsigned)j * 4u + iq;
            if (m < cur_bits || (m == cur_bits && idx < cur_idx)) {
                cur_bits = m; cur_idx = idx;
            }
        }

        // Warp reduce. Value tie -> smaller index (global first occurrence).
        #pragma unroll
        for (int o = 16; o > 0; o >>= 1) {
            s_sum += __shfl_xor_sync(0xffffffffu, s_sum, o);
            e_sum += __shfl_xor_sync(0xffffffffu, e_sum, o);
            const unsigned ob = __shfl_xor_sync(0xffffffffu, cur_bits, o);
            const unsigned oi = __shfl_xor_sync(0xffffffffu, cur_idx,  o);
            if (ob < cur_bits || (ob == cur_bits && oi < cur_idx)) {
                cur_bits = ob; cur_idx = oi;
            }
        }

        if (lid == 0) { sh_s[p][wid] = s_sum; sh_e[p][wid] = e_sum;
                        sh_b[p][wid] = cur_bits; sh_i[p][wid] = cur_idx; }
        __syncthreads();   // the ONLY per-row barrier

        // Warp 0 combines buffer p and retires the row while warps 1..15
        // stream the next row's loads.
        if (wid == 0) {
            const bool live = (lid < NWARP);
            float S = live ? sh_s[p][lid] : 0.f;
            float E = live ? sh_e[p][lid] : 0.f;
            unsigned B = live ? sh_b[p][lid] : 0xffffffffu;
            unsigned I = live ? sh_i[p][lid] : 0xffffffffu;
            #pragma unroll
            for (int o = 8; o > 0; o >>= 1) {
                S += __shfl_xor_sync(0xffffffffu, S, o);
                E += __shfl_xor_sync(0xffffffffu, E, o);
                const unsigned ob = __shfl_xor_sync(0xffffffffu, B, o);
                const unsigned oi = __shfl_xor_sync(0xffffffffu, I, o);
                if (ob < B || (ob == B && oi < I)) { B = ob; I = oi; }
            }
            if (lid == 0) {
                const float xi = inp[(size_t)row * NUM_CLS + I];
                // r_b = S_b + (C-1)*log(E_b) - x[b, idx]
                g_row[row] = S + (float)(NUM_CLS - 1) * logf(E) - xi;
            }
        }
        // no second __syncthreads — double buffering makes it unnecessary
    }

    // Block done: publish and count. thread 0 (warp 0, lane 0) performed
    // every g_row write of this block, so its fence covers them.
    if (threadIdx.x == 0) {
        __threadfence();
        const unsigned prev = atomicAdd(&g_done, 1u);
        sh_last = (prev == (unsigned)(NBLOCKS - 1));
    }
    __syncthreads();

    // Last block performs the final deterministic reduction (g_row L2-hot).
    if (sh_last) {
        float s = 0.f;
        for (int i = threadIdx.x; i < BATCH; i += THREADS)
            s += __ldcg(&g_row[i]);

        #pragma unroll
        for (int o = 16; o > 0; o >>= 1)
            s += __shfl_xor_sync(0xffffffffu, s, o);

        __shared__ float sh_f[NWARP];
        if (lid == 0) sh_f[wid] = s;
        __syncthreads();

        if (wid == 0) {
            float tot = (lid < NWARP) ? sh_f[lid] : 0.f;
            #pragma unroll
            for (int o = 8; o > 0; o >>= 1)
                tot += __shfl_xor_sync(0xffffffffu, tot, o);
            if (lid == 0) {
                // loss = (RATIO / (B*(C-1))) * sum_b r_b ; RATIO = 1.0
                out[0] = tot * (1.0f / ((float)BATCH * (float)(NUM_CLS - 1)));
                g_done = 0;   // reset for next graph replay
            }
        }
    }
}

extern "C" void kernel_launch(void* const* d_in, const int* in_sizes, int n_in,
                              void* d_out, int out_size)
{
    const float* inp = (const float*)d_in[0];   // input  [B, C] f32
    const float* tgt = (const float*)d_in[1];   // target [B, C] f32
    float* out = (float*)d_out;                 // scalar f32

    rce_fused_kernel<<<NBLOCKS, THREADS>>>(inp, tgt, out);
}

// round 14
// speedup vs baseline: 1.1340x; 1.1340x over previous
#include <cuda_runtime.h>

#define NUM_CLS 32000
#define BATCH   4096
#define C4      (NUM_CLS / 4)   // 8000 float4 per row
#define THREADS 512
#define NWARP   (THREADS / 32)  // 16
#define NBLOCKS 592             // 148 SMs x 4 resident CTAs — persistent grid
#define FXSCALE 1048576.0f      // 2^20 fixed-point scale for the row results

// Deterministic fixed-point accumulator: integer atomicAdd is associative
// and commutative, so the result is bit-identical regardless of block
// completion order. Last block resets both for graph replays.
__device__ unsigned long long g_sum;
__device__ unsigned int       g_done;

__global__ __launch_bounds__(THREADS, 4)
void rce_fused_kernel(const float* __restrict__ inp,
                      const float* __restrict__ tgt,
                      float* __restrict__ out)
{
    const int wid = threadIdx.x >> 5;
    const int lid = threadIdx.x & 31;

    // Double-buffered per-warp partials (parity = row counter & 1).
    // The single per-row __syncthreads orders: writes of buffer p (iter k,
    // pre-barrier) -> reads of buffer p (iter k, post-barrier) -> next write
    // of buffer p (iter k+2, after barrier k+1). No second barrier needed.
    __shared__ float    sh_s[2][NWARP];
    __shared__ float    sh_e[2][NWARP];
    __shared__ unsigned sh_b[2][NWARP];
    __shared__ unsigned sh_i[2][NWARP];
    __shared__ bool     sh_last;

    // Block-local fixed-point sum of this block's row results
    // (live only in warp 0 lane 0).
    long long blk_sum = 0;

    int k = 0;
    for (int row = blockIdx.x; row < BATCH; row += NBLOCKS, ++k) {
        const int p = k & 1;
        const float4* ip = reinterpret_cast<const float4*>(inp + (size_t)row * NUM_CLS);
        const float4* tp = reinterpret_cast<const float4*>(tgt + (size_t)row * NUM_CLS);

        float s_sum = 0.f;                 // sum of x
        float e_sum = 0.f;                 // sum of exp(-x)
        unsigned cur_bits = 0xffffffffu;   // running min of target bits (t >= 0
        unsigned cur_idx  = 0u;            //  -> float bits order-preserving)

        #pragma unroll 4
        for (int i = threadIdx.x; i < C4; i += THREADS) {
            const float4 x = ip[i];
            const float4 t = tp[i];

            s_sum += (x.x + x.y) + (x.z + x.w);
            e_sum += (__expf(-x.x) + __expf(-x.y)) + (__expf(-x.z) + __expf(-x.w));

            const unsigned b0 = __float_as_uint(t.x);
            const unsigned b1 = __float_as_uint(t.y);
            const unsigned b2 = __float_as_uint(t.z);
            const unsigned b3 = __float_as_uint(t.w);
            // Quad-local argmin, first index wins ties.
            const unsigned m01 = min(b0, b1);
            const unsigned i01 = (b1 < b0) ? 1u : 0u;
            const unsigned m23 = min(b2, b3);
            const unsigned i23 = (b3 < b2) ? 3u : 2u;
            const unsigned m   = min(m01, m23);
            const unsigned iq  = (m23 < m01) ? i23 : i01;
            // Iterations ascend per thread -> strict < keeps earlier index.
            if (m < cur_bits) { cur_bits = m; cur_idx = (unsigned)i * 4u + iq; }
        }

        // Warp reduce. Value tie -> smaller index (global first occurrence).
        #pragma unroll
        for (int o = 16; o > 0; o >>= 1) {
            s_sum += __shfl_xor_sync(0xffffffffu, s_sum, o);
            e_sum += __shfl_xor_sync(0xffffffffu, e_sum, o);
            const unsigned ob = __shfl_xor_sync(0xffffffffu, cur_bits, o);
            const unsigned oi = __shfl_xor_sync(0xffffffffu, cur_idx,  o);
            if (ob < cur_bits || (ob == cur_bits && oi < cur_idx)) {
                cur_bits = ob; cur_idx = oi;
            }
        }

        if (lid == 0) { sh_s[p][wid] = s_sum; sh_e[p][wid] = e_sum;
                        sh_b[p][wid] = cur_bits; sh_i[p][wid] = cur_idx; }
        __syncthreads();   // the ONLY per-row barrier

        // Warp 0 combines buffer p and retires the row while warps 1..15
        // stream the next row's loads.
        if (wid == 0) {
            const bool live = (lid < NWARP);
            float S = live ? sh_s[p][lid] : 0.f;
            float E = live ? sh_e[p][lid] : 0.f;
            unsigned B = live ? sh_b[p][lid] : 0xffffffffu;
            unsigned I = live ? sh_i[p][lid] : 0xffffffffu;
            #pragma unroll
            for (int o = 8; o > 0; o >>= 1) {
                S += __shfl_xor_sync(0xffffffffu, S, o);
                E += __shfl_xor_sync(0xffffffffu, E, o);
                const unsigned ob = __shfl_xor_sync(0xffffffffu, B, o);
                const unsigned oi = __shfl_xor_sync(0xffffffffu, I, o);
                if (ob < B || (ob == B && oi < I)) { B = ob; I = oi; }
            }
            if (lid == 0) {
                const float xi = inp[(size_t)row * NUM_CLS + I];
                // r_b = S_b + (C-1)*log(E_b) - x[b, idx]
                const float r = S + (float)(NUM_CLS - 1) * logf(E) - xi;
                // Accumulate in 2^20 fixed point (deterministic add later).
                blk_sum += __float2ll_rn(r * FXSCALE);
            }
        }
        // no second __syncthreads — double buffering makes it unnecessary
    }

    // Block done: one integer atomic carries this block's whole contribution.
    if (threadIdx.x == 0) {
        atomicAdd(&g_sum, (unsigned long long)blk_sum);
        __threadfence();
        const unsigned prev = atomicAdd(&g_done, 1u);
        sh_last = (prev == (unsigned)(NBLOCKS - 1));
    }
    __syncthreads();

    // Last block: convert the fixed-point total and write the scalar output.
    if (sh_last && threadIdx.x == 0) {
        const long long total = (long long)g_sum;
        // loss = (RATIO / (B*(C-1))) * sum_b r_b ; RATIO = 1.0
        out[0] = (float)((double)total / (double)FXSCALE
                         / ((double)BATCH * (double)(NUM_CLS - 1)));
        g_sum  = 0ull;   // reset for next graph replay
        g_done = 0u;
    }
}

extern "C" void kernel_launch(void* const* d_in, const int* in_sizes, int n_in,
                              void* d_out, int out_size)
{
    const float* inp = (const float*)d_in[0];   // input  [B, C] f32
    const float* tgt = (const float*)d_in[1];   // target [B, C] f32
    float* out = (float*)d_out;                 // scalar f32

    rce_fused_kernel<<<NBLOCKS, THREADS>>>(inp, tgt, out);
}

// round 15
// speedup vs baseline: 1.1436x; 1.0085x over previous
#include <cuda_runtime.h>

#define NUM_CLS 32000
#define BATCH   4096
#define C4      (NUM_CLS / 4)   // 8000 float4 per row
#define THREADS 512
#define NWARP   (THREADS / 32)  // 16
#define NBLOCKS 592             // 148 SMs x 4 resident CTAs — persistent grid
#define MAXROWS 7               // ceil(4096/592)
#define FXSCALE 1048576.0f      // 2^20 fixed-point scale for the row results

// Deterministic fixed-point accumulator: integer atomicAdd is associative
// and commutative -> bit-identical result regardless of block completion
// order. Last block resets both for graph replays.
__device__ unsigned long long g_sum;
__device__ unsigned int       g_done;

__global__ __launch_bounds__(THREADS, 4)
void rce_fused_kernel(const float* __restrict__ inp,
                      const float* __restrict__ tgt,
                      float* __restrict__ out)
{
    const int wid = threadIdx.x >> 5;
    const int lid = threadIdx.x & 31;

    // Per-row per-warp partials for ALL of this block's rows. No barrier in
    // the row loop at all: each warp writes only its own slot, and all
    // cross-warp combining is deferred to a single sync at the end.
    __shared__ float     sh_s[MAXROWS][NWARP];
    __shared__ float     sh_e[MAXROWS][NWARP];
    __shared__ unsigned  sh_b[MAXROWS][NWARP];
    __shared__ unsigned  sh_i[MAXROWS][NWARP];
    __shared__ long long sh_fx[MAXROWS];
    __shared__ bool      sh_last;

    int k = 0;
    for (int row = blockIdx.x; row < BATCH; row += NBLOCKS, ++k) {
        const float4* ip = reinterpret_cast<const float4*>(inp + (size_t)row * NUM_CLS);
        const float4* tp = reinterpret_cast<const float4*>(tgt + (size_t)row * NUM_CLS);

        float s_sum = 0.f;                 // sum of x
        float e_sum = 0.f;                 // sum of exp(-x)
        unsigned cur_bits = 0xffffffffu;   // running min of target bits (t >= 0
        unsigned cur_idx  = 0u;            //  -> float bits order-preserving)

        #pragma unroll 4
        for (int i = threadIdx.x; i < C4; i += THREADS) {
            const float4 x = ip[i];
            const float4 t = tp[i];

            s_sum += (x.x + x.y) + (x.z + x.w);
            e_sum += (__expf(-x.x) + __expf(-x.y)) + (__expf(-x.z) + __expf(-x.w));

            const unsigned b0 = __float_as_uint(t.x);
            const unsigned b1 = __float_as_uint(t.y);
            const unsigned b2 = __float_as_uint(t.z);
            const unsigned b3 = __float_as_uint(t.w);
            // Quad-local argmin, first index wins ties.
            const unsigned m01 = min(b0, b1);
            const unsigned i01 = (b1 < b0) ? 1u : 0u;
            const unsigned m23 = min(b2, b3);
            const unsigned i23 = (b3 < b2) ? 3u : 2u;
            const unsigned m   = min(m01, m23);
            const unsigned iq  = (m23 < m01) ? i23 : i01;
            // Iterations ascend per thread -> strict < keeps earlier index.
            if (m < cur_bits) { cur_bits = m; cur_idx = (unsigned)i * 4u + iq; }
        }

        // Warp reduce. Value tie -> smaller index (global first occurrence).
        #pragma unroll
        for (int o = 16; o > 0; o >>= 1) {
            s_sum += __shfl_xor_sync(0xffffffffu, s_sum, o);
            e_sum += __shfl_xor_sync(0xffffffffu, e_sum, o);
            const unsigned ob = __shfl_xor_sync(0xffffffffu, cur_bits, o);
            const unsigned oi = __shfl_xor_sync(0xffffffffu, cur_idx,  o);
            if (ob < cur_bits || (ob == cur_bits && oi < cur_idx)) {
                cur_bits = ob; cur_idx = oi;
            }
        }

        // Deposit this warp's partial for row k. No barrier — next row starts
        // immediately; warps drift freely.
        if (lid == 0) { sh_s[k][wid] = s_sum; sh_e[k][wid] = e_sum;
                        sh_b[k][wid] = cur_bits; sh_i[k][wid] = cur_idx; }
    }
    const int nrows = k;   // 6 or 7

    __syncthreads();   // the ONLY barrier before the final publish

    // Combine phase: warp w retires row w (parallel combines + xi loads).
    if (wid < nrows) {
        const int row = blockIdx.x + wid * NBLOCKS;
        const bool live = (lid < NWARP);
        float S = live ? sh_s[wid][lid] : 0.f;
        float E = live ? sh_e[wid][lid] : 0.f;
        unsigned B = live ? sh_b[wid][lid] : 0xffffffffu;
        unsigned I = live ? sh_i[wid][lid] : 0xffffffffu;
        #pragma unroll
        for (int o = 8; o > 0; o >>= 1) {
            S += __shfl_xor_sync(0xffffffffu, S, o);
            E += __shfl_xor_sync(0xffffffffu, E, o);
            const unsigned ob = __shfl_xor_sync(0xffffffffu, B, o);
            const unsigned oi = __shfl_xor_sync(0xffffffffu, I, o);
            if (ob < B || (ob == B && oi < I)) { B = ob; I = oi; }
        }
        if (lid == 0) {
            const float xi = inp[(size_t)row * NUM_CLS + I];
            // r_b = S_b + (C-1)*log(E_b) - x[b, idx]
            const float r = S + (float)(NUM_CLS - 1) * logf(E) - xi;
            sh_fx[wid] = (long long)__float2ll_rn(r * FXSCALE);
        }
    }
    __syncthreads();

    // Thread 0: sum the <=7 fixed-point row values, one atomic publish.
    if (threadIdx.x == 0) {
        long long blk_sum = 0;
        for (int r = 0; r < nrows; ++r) blk_sum += sh_fx[r];
        atomicAdd(&g_sum, (unsigned long long)blk_sum);
        __threadfence();
        const unsigned prev = atomicAdd(&g_done, 1u);
        sh_last = (prev == (unsigned)(NBLOCKS - 1));
    }
    __syncthreads();

    // Last block: convert the fixed-point total and write the scalar output.
    if (sh_last && threadIdx.x == 0) {
        const long long total = (long long)g_sum;
        // loss = (RATIO / (B*(C-1))) * sum_b r_b ; RATIO = 1.0
        out[0] = (float)((double)total / (double)FXSCALE
                         / ((double)BATCH * (double)(NUM_CLS - 1)));
        g_sum  = 0ull;   // reset for next graph replay
        g_done = 0u;
    }
}

extern "C" void kernel_launch(void* const* d_in, const int* in_sizes, int n_in,
                              void* d_out, int out_size)
{
    const float* inp = (const float*)d_in[0];   // input  [B, C] f32
    const float* tgt = (const float*)d_in[1];   // target [B, C] f32
    float* out = (float*)d_out;                 // scalar f32

    rce_fused_kernel<<<NBLOCKS, THREADS>>>(inp, tgt, out);
}